// round 2
// baseline (speedup 1.0000x reference)
#include <cuda_runtime.h>

namespace {
constexpr int S_TOT = 22743;   // 3*(76^2 + 38^2 + 19^2)
constexpr int S1    = 17328;   // 76*76*3
constexpr int C     = 85;
constexpr int NB    = 1184;    // 8 blocks/SM * 148 SMs
constexpr int TPB   = 256;
constexpr int WPB   = TPB / 32;
}

// partials: [NB][5] = {sum_obj, sum_xy, sum_wh, sum_cls, cnt}
__device__ float    g_partials[NB * 5];
__device__ unsigned g_count = 0;   // reset to 0 by last block each launch

__device__ __forceinline__ float bce_f(float p, float t) {
    // p in (1e-4, 1-1e-4) -> log clip at -100 never fires
    float lp = __logf(p);
    float lq = __logf(1.0f - p);
    return -fmaf(t, lp - lq, lq);   // -(t*lp + (1-t)*lq)
}

__global__ __launch_bounds__(TPB) void yolo_fused(const float* __restrict__ x,
                                                  const float* __restrict__ tg,
                                                  int B, float inv_obj_div,
                                                  float* __restrict__ out) {
    const int lane  = threadIdx.x & 31;
    const int wid   = threadIdx.x >> 5;
    const int gwarp = blockIdx.x * WPB + wid;
    const int nwarp = NB * WPB;
    const int rowC  = S_TOT * C;                // per-batch stride (floats)

    float a_obj = 0.f, a_xy = 0.f, a_wh = 0.f, a_cls = 0.f, a_cnt = 0.f;

    // Grid-stride over spatial index s; batch b is the inner (uniform) loop.
    for (int s = gwarp; s < S_TOT; s += nwarp) {
        if (s < S1) {
            // dense objectness slab: every channel of every batch row at this s
            const int  c0 = lane, c1 = lane + 32, c2 = lane + 64;
            const bool v2 = (c2 < C);
            int base = s * C;
            #pragma unroll 4
            for (int b = 0; b < B; ++b, base += rowC) {
                float p0 = x[base + c0];
                float t0 = tg[base + c0];
                float p1 = x[base + c1];
                float t1 = tg[base + c1];
                float p2 = v2 ? x[base + c2]  : 0.5f;
                float t2 = v2 ? tg[base + c2] : 0.5f;
                float b0 = bce_f(p0, t0);
                float b1 = bce_f(p1, t1);
                float b2 = v2 ? bce_f(p2, t2) : 0.0f;
                a_obj += b0 + b1 + b2;

                float t4 = __shfl_sync(0xffffffffu, t0, 4);
                if (t4 > 0.0f) {
                    if (c0 < 2)        a_xy  += b0;
                    else if (c0 < 4)   a_wh  += b0;
                    else if (c0 == 4) { a_cls += b0; a_cnt += 1.0f; }
                }
            }
        } else {
            // tail rows: only xy/wh/cls terms; one 4-byte probe per (b,s),
            // all B probes issued in parallel across lanes
            const int base = s * C;
            for (int bb = 0; bb < B; bb += 32) {
                int   b  = bb + lane;
                float t4 = 0.0f;
                if (b < B) t4 = tg[base + b * rowC + 4];
                unsigned act = __ballot_sync(0xffffffffu, t4 > 0.0f);
                while (act) {
                    int bpos = __ffs(act) - 1;
                    act &= act - 1;
                    int rb = base + (bb + bpos) * rowC;
                    if (lane < 5) {
                        float bl = bce_f(x[rb + lane], tg[rb + lane]);
                        if (lane < 2)      a_xy += bl;
                        else if (lane < 4) a_wh += bl;
                        else             { a_cls += bl; a_cnt += 1.0f; }
                    }
                }
            }
        }
    }

    // ── warp reduction (5 scalars) ──
    #pragma unroll
    for (int off = 16; off; off >>= 1) {
        a_obj += __shfl_xor_sync(0xffffffffu, a_obj, off);
        a_xy  += __shfl_xor_sync(0xffffffffu, a_xy,  off);
        a_wh  += __shfl_xor_sync(0xffffffffu, a_wh,  off);
        a_cls += __shfl_xor_sync(0xffffffffu, a_cls, off);
        a_cnt += __shfl_xor_sync(0xffffffffu, a_cnt, off);
    }
    __shared__ float sm[WPB][5];
    if (lane == 0) {
        sm[wid][0] = a_obj; sm[wid][1] = a_xy; sm[wid][2] = a_wh;
        sm[wid][3] = a_cls; sm[wid][4] = a_cnt;
    }
    __syncthreads();
    if (threadIdx.x < 32) {
        #pragma unroll
        for (int k = 0; k < 5; k++) {
            float v = (lane < WPB) ? sm[lane][k] : 0.0f;
            #pragma unroll
            for (int off = 4; off; off >>= 1)
                v += __shfl_xor_sync(0xffffffffu, v, off);
            if (lane == 0) g_partials[blockIdx.x * 5 + k] = v;
        }
    }

    // ── last-block-done final reduction (threadFenceReduction pattern) ──
    __shared__ bool isLast;
    if (threadIdx.x == 0) {
        __threadfence();                       // publish g_partials
        unsigned old = atomicAdd(&g_count, 1u);
        isLast = (old == (unsigned)gridDim.x - 1u);
    }
    __syncthreads();
    if (isLast) {
        const volatile float* gp = g_partials; // bypass any stale caching
        float loc[5] = {0.f, 0.f, 0.f, 0.f, 0.f};
        for (int j = threadIdx.x; j < NB; j += TPB) {
            #pragma unroll
            for (int k = 0; k < 5; k++) loc[k] += gp[j * 5 + k];
        }
        __shared__ float red[TPB];
        float tot[5];
        #pragma unroll
        for (int k = 0; k < 5; k++) {
            red[threadIdx.x] = loc[k];
            __syncthreads();
            for (int st = TPB / 2; st; st >>= 1) {
                if (threadIdx.x < st) red[threadIdx.x] += red[threadIdx.x + st];
                __syncthreads();
            }
            tot[k] = red[0];
            __syncthreads();
        }
        if (threadIdx.x == 0) {
            float cnt   = fmaxf(tot[4], 1.0f);
            float inv_c = 1.0f / cnt;
            out[0] = tot[0] * inv_obj_div
                   + (tot[1] + tot[2]) * 0.5f * inv_c
                   + tot[3] * inv_c;
            g_count = 0;                       // reset for next (graph) replay
        }
    }
}

extern "C" void kernel_launch(void* const* d_in, const int* in_sizes, int n_in,
                              void* d_out, int out_size) {
    const float* x  = (const float*)d_in[0];
    const float* tg = (const float*)d_in[1];
    const int rows  = in_sizes[0] / C;          // B * S
    const int Bn    = rows / S_TOT;             // batch
    const float inv_obj_div = 1.0f / ((float)Bn * (float)S1 * (float)C);

    yolo_fused<<<NB, TPB>>>(x, tg, Bn, inv_obj_div, (float*)d_out);
}

// round 3
// speedup vs baseline: 1.1591x; 1.1591x over previous
#include <cuda_runtime.h>

namespace {
constexpr int S_TOT = 22743;   // 3*(76^2 + 38^2 + 19^2)
constexpr int S1    = 17328;   // 76*76*3
constexpr int C     = 85;
constexpr int LEN   = S1 * C;          // dense slab floats per batch (divisible by 4)
constexpr int TPB   = 256;
constexpr int MAXNB = 4096;
}

// partials: [grid][5] = {sum_obj, sum_xy, sum_wh, sum_cls, cnt}
__device__ float    g_partials[MAXNB * 5];
__device__ unsigned g_count = 0;   // reset by last block each launch

__device__ __forceinline__ float bce_f(float p, float t) {
    // p in (1e-4, 1-1e-4) -> the -100 log clip never fires
    float lp = __logf(p);
    float lq = __logf(1.0f - p);
    return -fmaf(t, lp - lq, lq);   // -(t*lp + (1-t)*lq)
}

__global__ __launch_bounds__(TPB) void yolo_fused(const float* __restrict__ x,
                                                  const float* __restrict__ tg,
                                                  int B, float inv_obj_div,
                                                  float* __restrict__ out) {
    const int gtid = blockIdx.x * TPB + threadIdx.x;
    const int NT   = gridDim.x * TPB;
    const int strideB = S_TOT * C;          // floats per batch

    float a_obj = 0.f, a_xy = 0.f, a_wh = 0.f, a_cls = 0.f, a_cnt = 0.f;

    // ───────── Pass A: flat vectorized BCE sum over each batch's dense slab ─────────
    for (int b = 0; b < B; ++b) {
        const int base = b * strideB;
        const int pad  = (4 - (base & 3)) & 3;        // scalars to reach 16B alignment
        const int nv4  = (LEN - pad) >> 2;
        const int rem  = (LEN - pad) & 3;

        const float4* __restrict__ x4 = (const float4*)(x  + base + pad);
        const float4* __restrict__ t4 = (const float4*)(tg + base + pad);

        for (int v = gtid; v < nv4; v += NT) {
            float4 p = x4[v];
            float4 t = t4[v];
            float b0 = bce_f(p.x, t.x);
            float b1 = bce_f(p.y, t.y);
            float b2 = bce_f(p.z, t.z);
            float b3 = bce_f(p.w, t.w);
            a_obj += (b0 + b1) + (b2 + b3);
        }
        // head peel (< 4 elems)
        if (gtid < pad)
            a_obj += bce_f(x[base + gtid], tg[base + gtid]);
        // tail peel (< 4 elems)
        if (gtid >= 8 && gtid < 8 + rem) {
            int idx = base + pad + 4 * nv4 + (gtid - 8);
            a_obj += bce_f(x[idx], tg[idx]);
        }
    }

    // ───────── Pass B: gated xy/wh/cls terms over ALL rows (one row / thread) ─────────
    const int rows = B * S_TOT;
    for (int r = gtid; r < rows; r += NT) {
        const int rb = r * C;
        float t4v = tg[rb + 4];
        if (t4v > 0.0f) {
            a_xy  += bce_f(x[rb + 0], tg[rb + 0]) + bce_f(x[rb + 1], tg[rb + 1]);
            a_wh  += bce_f(x[rb + 2], tg[rb + 2]) + bce_f(x[rb + 3], tg[rb + 3]);
            a_cls += bce_f(x[rb + 4], t4v);
            a_cnt += 1.0f;
        }
    }

    // ───────── block reduction (5 scalars) ─────────
    const int lane = threadIdx.x & 31;
    const int wid  = threadIdx.x >> 5;
    #pragma unroll
    for (int off = 16; off; off >>= 1) {
        a_obj += __shfl_xor_sync(0xffffffffu, a_obj, off);
        a_xy  += __shfl_xor_sync(0xffffffffu, a_xy,  off);
        a_wh  += __shfl_xor_sync(0xffffffffu, a_wh,  off);
        a_cls += __shfl_xor_sync(0xffffffffu, a_cls, off);
        a_cnt += __shfl_xor_sync(0xffffffffu, a_cnt, off);
    }
    __shared__ float sm[TPB / 32][5];
    if (lane == 0) {
        sm[wid][0] = a_obj; sm[wid][1] = a_xy; sm[wid][2] = a_wh;
        sm[wid][3] = a_cls; sm[wid][4] = a_cnt;
    }
    __syncthreads();
    if (threadIdx.x < 32) {
        #pragma unroll
        for (int k = 0; k < 5; k++) {
            float v = (lane < TPB / 32) ? sm[lane][k] : 0.0f;
            #pragma unroll
            for (int off = 4; off; off >>= 1)
                v += __shfl_xor_sync(0xffffffffu, v, off);
            if (lane == 0) g_partials[blockIdx.x * 5 + k] = v;
        }
    }

    // ───────── last-block final reduction ─────────
    __shared__ bool isLast;
    if (threadIdx.x == 0) {
        __threadfence();
        unsigned old = atomicAdd(&g_count, 1u);
        isLast = (old == gridDim.x - 1u);
    }
    __syncthreads();
    if (isLast) {
        const volatile float* gp = g_partials;
        float loc[5] = {0.f, 0.f, 0.f, 0.f, 0.f};
        for (int j = threadIdx.x; j < (int)gridDim.x; j += TPB) {
            #pragma unroll
            for (int k = 0; k < 5; k++) loc[k] += gp[j * 5 + k];
        }
        __shared__ float red[TPB];
        float tot[5];
        #pragma unroll
        for (int k = 0; k < 5; k++) {
            red[threadIdx.x] = loc[k];
            __syncthreads();
            for (int st = TPB / 2; st; st >>= 1) {
                if (threadIdx.x < st) red[threadIdx.x] += red[threadIdx.x + st];
                __syncthreads();
            }
            tot[k] = red[0];
            __syncthreads();
        }
        if (threadIdx.x == 0) {
            float cnt   = fmaxf(tot[4], 1.0f);
            float inv_c = 1.0f / cnt;
            out[0] = tot[0] * inv_obj_div
                   + (tot[1] + tot[2]) * 0.5f * inv_c
                   + tot[3] * inv_c;
            g_count = 0;                     // reset for next graph replay
        }
    }
}

extern "C" void kernel_launch(void* const* d_in, const int* in_sizes, int n_in,
                              void* d_out, int out_size) {
    const float* x  = (const float*)d_in[0];
    const float* tg = (const float*)d_in[1];
    const int rows  = in_sizes[0] / C;          // B * S
    const int Bn    = rows / S_TOT;             // batch
    const float inv_obj_div = 1.0f / ((float)Bn * (float)S1 * (float)C);

    // size the grid to exactly one resident wave (host-side, capture-time only)
    int dev = 0, smCount = 148, bpm = 4;
    cudaGetDevice(&dev);
    cudaDeviceGetAttribute(&smCount, cudaDevAttrMultiProcessorCount, dev);
    cudaOccupancyMaxActiveBlocksPerMultiprocessor(&bpm, yolo_fused, TPB, 0);
    int nb = smCount * (bpm > 0 ? bpm : 1);
    if (nb > MAXNB) nb = MAXNB;

    yolo_fused<<<nb, TPB>>>(x, tg, Bn, inv_obj_div, (float*)d_out);
}

// round 4
// speedup vs baseline: 1.4008x; 1.2085x over previous
#include <cuda_runtime.h>

namespace {
constexpr int S_TOT   = 22743;           // 3*(76^2 + 38^2 + 19^2)
constexpr int S1      = 17328;           // 76*76*3
constexpr int C       = 85;
constexpr int LEN     = S1 * C;          // 1,472,880 dense floats per batch
constexpr int STRIDEB = S_TOT * C;       // 1,933,155 floats per batch
constexpr int V4U     = (LEN - 3) / 4;   // 368,219 uniform float4s per batch
constexpr int OFF4_D  = (STRIDEB + 1) / 4;  // 483,289 (pad delta +1)
constexpr int OFF4_D3 = (STRIDEB - 3) / 4;  // 483,288 (pad delta -3, b%4==3)
constexpr int TPB     = 256;
constexpr int MAXNB   = 4096;
}

__device__ float    g_partials[MAXNB * 5];
__device__ unsigned g_count = 0;

// BCE in log2 units: returns t*(lg2 p - lg2 q) + lg2 q ; final loss = -ln2 * sum
__device__ __forceinline__ float bce_l2(float p, float t) {
    float lp = __log2f(p);
    float lq = __log2f(1.0f - p);
    return fmaf(t, lp - lq, lq);
}

__device__ __forceinline__ float bce4_l2(float4 p, float4 t) {
    float b0 = bce_l2(p.x, t.x);
    float b1 = bce_l2(p.y, t.y);
    float b2 = bce_l2(p.z, t.z);
    float b3 = bce_l2(p.w, t.w);
    return (b0 + b1) + (b2 + b3);
}

__global__ __launch_bounds__(TPB) void yolo_fused(const float* __restrict__ x,
                                                  const float* __restrict__ tg,
                                                  int B, float inv_obj_div,
                                                  float* __restrict__ out) {
    const int gtid = blockIdx.x * TPB + threadIdx.x;
    const int NT   = gridDim.x * TPB;
    const int W4   = B * V4U;

    const float4* __restrict__ x4 = (const float4*)x;
    const float4* __restrict__ t4 = (const float4*)tg;

    float a_obj = 0.f, a_xy = 0.f, a_wh = 0.f, a_cls = 0.f, a_cnt = 0.f;

    // ── Pass A: flat dense-slab BCE, batch carried incrementally (no div) ──
    // gtid < NT <= ~400k < V4U, so every thread starts in batch 0.
    int v = gtid, b = 0, off4 = 0;

#define YSTEP()                                                    \
    do {                                                           \
        v += NT;                                                   \
        if (v >= V4U) {                                            \
            v -= V4U;                                              \
            off4 += ((b & 3) == 3) ? OFF4_D3 : OFF4_D;             \
            ++b;                                                   \
        }                                                          \
    } while (0)

    int w = gtid;
    for (; w + 3 * NT < W4; w += 4 * NT) {
        int a0 = off4 + v; YSTEP();
        int a1 = off4 + v; YSTEP();
        int a2 = off4 + v; YSTEP();
        int a3 = off4 + v; YSTEP();
        float4 p0 = x4[a0], q0 = t4[a0];
        float4 p1 = x4[a1], q1 = t4[a1];
        float4 p2 = x4[a2], q2 = t4[a2];
        float4 p3 = x4[a3], q3 = t4[a3];
        a_obj += bce4_l2(p0, q0) + bce4_l2(p1, q1);
        a_obj += bce4_l2(p2, q2) + bce4_l2(p3, q3);
    }
    for (; w < W4; w += NT) {
        int a0 = off4 + v; YSTEP();
        a_obj += bce4_l2(x4[a0], t4[a0]);
    }
#undef YSTEP

    // leftover scalars: exactly 4 per batch (alignment head + tail remainder)
    if (gtid < 4 * B) {
        int bb  = gtid >> 2, j = gtid & 3;
        int pad = bb & 3;
        int base = bb * STRIDEB;
        int idx = (j < pad) ? (base + j)
                            : (base + pad + 4 * V4U + (j - pad));
        a_obj += bce_l2(x[idx], tg[idx]);
    }

    // ── Pass B: gated xy/wh/cls terms, one row per thread ──
    const int rows = B * S_TOT;
    for (int r = gtid; r < rows; r += NT) {
        const int rb = r * C;
        float t4v = tg[rb + 4];
        if (t4v > 0.0f) {
            a_xy  += bce_l2(x[rb + 0], tg[rb + 0]) + bce_l2(x[rb + 1], tg[rb + 1]);
            a_wh  += bce_l2(x[rb + 2], tg[rb + 2]) + bce_l2(x[rb + 3], tg[rb + 3]);
            a_cls += bce_l2(x[rb + 4], t4v);
            a_cnt += 1.0f;
        }
    }

    // ── block reduction (5 scalars) ──
    const int lane = threadIdx.x & 31;
    const int wid  = threadIdx.x >> 5;
    #pragma unroll
    for (int off = 16; off; off >>= 1) {
        a_obj += __shfl_xor_sync(0xffffffffu, a_obj, off);
        a_xy  += __shfl_xor_sync(0xffffffffu, a_xy,  off);
        a_wh  += __shfl_xor_sync(0xffffffffu, a_wh,  off);
        a_cls += __shfl_xor_sync(0xffffffffu, a_cls, off);
        a_cnt += __shfl_xor_sync(0xffffffffu, a_cnt, off);
    }
    __shared__ float sm[TPB / 32][5];
    if (lane == 0) {
        sm[wid][0] = a_obj; sm[wid][1] = a_xy; sm[wid][2] = a_wh;
        sm[wid][3] = a_cls; sm[wid][4] = a_cnt;
    }
    __syncthreads();
    if (threadIdx.x < 32) {
        #pragma unroll
        for (int k = 0; k < 5; k++) {
            float vv = (lane < TPB / 32) ? sm[lane][k] : 0.0f;
            #pragma unroll
            for (int off = 4; off; off >>= 1)
                vv += __shfl_xor_sync(0xffffffffu, vv, off);
            if (lane == 0) g_partials[blockIdx.x * 5 + k] = vv;
        }
    }

    // ── last-block final reduction ──
    __shared__ bool isLast;
    if (threadIdx.x == 0) {
        __threadfence();
        unsigned old = atomicAdd(&g_count, 1u);
        isLast = (old == gridDim.x - 1u);
    }
    __syncthreads();
    if (isLast) {
        const volatile float* gp = g_partials;
        float loc[5] = {0.f, 0.f, 0.f, 0.f, 0.f};
        for (int j = threadIdx.x; j < (int)gridDim.x; j += TPB) {
            #pragma unroll
            for (int k = 0; k < 5; k++) loc[k] += gp[j * 5 + k];
        }
        __shared__ float red[TPB];
        float tot[5];
        #pragma unroll
        for (int k = 0; k < 5; k++) {
            red[threadIdx.x] = loc[k];
            __syncthreads();
            for (int st = TPB / 2; st; st >>= 1) {
                if (threadIdx.x < st) red[threadIdx.x] += red[threadIdx.x + st];
                __syncthreads();
            }
            tot[k] = red[0];
            __syncthreads();
        }
        if (threadIdx.x == 0) {
            constexpr float LN2 = 0.69314718055994530942f;
            float cnt   = fmaxf(tot[4], 1.0f);
            float inv_c = 1.0f / cnt;
            // accumulators are in lg2 units and negative; loss = -ln2 * (...)
            out[0] = -LN2 * (tot[0] * inv_obj_div
                             + (tot[1] + tot[2]) * 0.5f * inv_c
                             + tot[3] * inv_c);
            g_count = 0;
        }
    }
}

extern "C" void kernel_launch(void* const* d_in, const int* in_sizes, int n_in,
                              void* d_out, int out_size) {
    const float* x  = (const float*)d_in[0];
    const float* tg = (const float*)d_in[1];
    const int rows  = in_sizes[0] / C;     // B * S
    const int Bn    = rows / S_TOT;        // batch
    const float inv_obj_div = 1.0f / ((float)Bn * (float)S1 * (float)C);

    int dev = 0, smCount = 148, bpm = 4;
    cudaGetDevice(&dev);
    cudaDeviceGetAttribute(&smCount, cudaDevAttrMultiProcessorCount, dev);
    cudaOccupancyMaxActiveBlocksPerMultiprocessor(&bpm, yolo_fused, TPB, 0);
    int nb = smCount * (bpm > 0 ? bpm : 1);
    if (nb > MAXNB) nb = MAXNB;

    yolo_fused<<<nb, TPB>>>(x, tg, Bn, inv_obj_div, (float*)d_out);
}

// round 5
// speedup vs baseline: 1.5484x; 1.1054x over previous
#include <cuda_runtime.h>

namespace {
constexpr int S_TOT   = 22743;           // 3*(76^2 + 38^2 + 19^2)
constexpr int S1      = 17328;           // 76*76*3
constexpr int C       = 85;
constexpr int LEN     = S1 * C;          // 1,472,880 dense floats per batch
constexpr int STRIDEB = S_TOT * C;       // 1,933,155 floats per batch
constexpr int V4U     = (LEN - 3) / 4;   // 368,219 uniform float4s per batch
constexpr int OFF4_D  = (STRIDEB + 1) / 4;  // 483,289 (pad delta +1)
constexpr int OFF4_D3 = (STRIDEB - 3) / 4;  // 483,288 (pad delta -3, b%4==3)
constexpr int TPB     = 256;
constexpr int MAXNB   = 4096;
}

__device__ float    g_partials[MAXNB * 5];
__device__ unsigned g_count = 0;

// BCE in log2 units: returns t*(lg2 p - lg2 q) + lg2 q ; final loss = -ln2 * sum
__device__ __forceinline__ float bce_l2(float p, float t) {
    float lp = __log2f(p);
    float lq = __log2f(1.0f - p);
    return fmaf(t, lp - lq, lq);
}

__device__ __forceinline__ float bce4_l2(float4 p, float4 t) {
    float b0 = bce_l2(p.x, t.x);
    float b1 = bce_l2(p.y, t.y);
    float b2 = bce_l2(p.z, t.z);
    float b3 = bce_l2(p.w, t.w);
    return (b0 + b1) + (b2 + b3);
}

__global__ __launch_bounds__(TPB) void yolo_fused(const float* __restrict__ x,
                                                  const float* __restrict__ tg,
                                                  int B, float inv_obj_div,
                                                  float* __restrict__ out) {
    const int gtid = blockIdx.x * TPB + threadIdx.x;
    const int NT   = gridDim.x * TPB;
    const int W4   = B * V4U;
    const int rows = B * S_TOT;

    const float4* __restrict__ x4 = (const float4*)x;
    const float4* __restrict__ t4 = (const float4*)tg;

    float a_obj = 0.f, a_xy = 0.f, a_wh = 0.f, a_cls = 0.f, a_cnt = 0.f;

    // ── Prefetch Pass-B probes (issued now, consumed after Pass A: latency
    //    fully hidden under the streaming loop) ──
    const int r0 = gtid;           // always < rows (NT << rows)
    const int r1 = gtid + NT;
    float pf0 = __ldg(tg + r0 * C + 4);
    float pf1 = (r1 < rows) ? __ldg(tg + r1 * C + 4) : 0.0f;

    // ── Pass A: flat dense-slab BCE, batch carried incrementally (no div) ──
    int v = gtid, b = 0, off4 = 0;

#define YSTEP()                                                    \
    do {                                                           \
        v += NT;                                                   \
        if (v >= V4U) {                                            \
            v -= V4U;                                              \
            off4 += ((b & 3) == 3) ? OFF4_D3 : OFF4_D;             \
            ++b;                                                   \
        }                                                          \
    } while (0)

    int w = gtid;
    for (; w + 3 * NT < W4; w += 4 * NT) {
        int a0 = off4 + v; YSTEP();
        int a1 = off4 + v; YSTEP();
        int a2 = off4 + v; YSTEP();
        int a3 = off4 + v; YSTEP();
        // x stream: evict-first (no reuse) so tg can stay resident in L2
        float4 p0 = __ldcs(x4 + a0), q0 = t4[a0];
        float4 p1 = __ldcs(x4 + a1), q1 = t4[a1];
        float4 p2 = __ldcs(x4 + a2), q2 = t4[a2];
        float4 p3 = __ldcs(x4 + a3), q3 = t4[a3];
        a_obj += bce4_l2(p0, q0) + bce4_l2(p1, q1);
        a_obj += bce4_l2(p2, q2) + bce4_l2(p3, q3);
    }
    for (; w < W4; w += NT) {
        int a0 = off4 + v; YSTEP();
        a_obj += bce4_l2(__ldcs(x4 + a0), t4[a0]);
    }
#undef YSTEP

    // leftover scalars: exactly 4 per batch (alignment head + tail remainder)
    if (gtid < 4 * B) {
        int bb  = gtid >> 2, j = gtid & 3;
        int pad = bb & 3;
        int base = bb * STRIDEB;
        int idx = (j < pad) ? (base + j)
                            : (base + pad + 4 * V4U + (j - pad));
        a_obj += bce_l2(x[idx], tg[idx]);
    }

    // ── Pass B: gated xy/wh/cls terms (probes already in flight) ──
    {
        if (pf0 > 0.0f) {
            const int rb = r0 * C;
            a_xy  += bce_l2(__ldg(x + rb + 0), __ldg(tg + rb + 0))
                   + bce_l2(__ldg(x + rb + 1), __ldg(tg + rb + 1));
            a_wh  += bce_l2(__ldg(x + rb + 2), __ldg(tg + rb + 2))
                   + bce_l2(__ldg(x + rb + 3), __ldg(tg + rb + 3));
            a_cls += bce_l2(__ldg(x + rb + 4), pf0);
            a_cnt += 1.0f;
        }
        if (r1 < rows && pf1 > 0.0f) {
            const int rb = r1 * C;
            a_xy  += bce_l2(__ldg(x + rb + 0), __ldg(tg + rb + 0))
                   + bce_l2(__ldg(x + rb + 1), __ldg(tg + rb + 1));
            a_wh  += bce_l2(__ldg(x + rb + 2), __ldg(tg + rb + 2))
                   + bce_l2(__ldg(x + rb + 3), __ldg(tg + rb + 3));
            a_cls += bce_l2(__ldg(x + rb + 4), pf1);
            a_cnt += 1.0f;
        }
        // generic remainder (only if grid is small enough that 2*NT < rows)
        for (int r = gtid + 2 * NT; r < rows; r += NT) {
            const int rb = r * C;
            float t4v = __ldg(tg + rb + 4);
            if (t4v > 0.0f) {
                a_xy  += bce_l2(x[rb + 0], tg[rb + 0]) + bce_l2(x[rb + 1], tg[rb + 1]);
                a_wh  += bce_l2(x[rb + 2], tg[rb + 2]) + bce_l2(x[rb + 3], tg[rb + 3]);
                a_cls += bce_l2(x[rb + 4], t4v);
                a_cnt += 1.0f;
            }
        }
    }

    // ── block reduction (5 scalars) ──
    const int lane = threadIdx.x & 31;
    const int wid  = threadIdx.x >> 5;
    #pragma unroll
    for (int off = 16; off; off >>= 1) {
        a_obj += __shfl_xor_sync(0xffffffffu, a_obj, off);
        a_xy  += __shfl_xor_sync(0xffffffffu, a_xy,  off);
        a_wh  += __shfl_xor_sync(0xffffffffu, a_wh,  off);
        a_cls += __shfl_xor_sync(0xffffffffu, a_cls, off);
        a_cnt += __shfl_xor_sync(0xffffffffu, a_cnt, off);
    }
    __shared__ float sm[TPB / 32][5];
    if (lane == 0) {
        sm[wid][0] = a_obj; sm[wid][1] = a_xy; sm[wid][2] = a_wh;
        sm[wid][3] = a_cls; sm[wid][4] = a_cnt;
    }
    __syncthreads();
    if (threadIdx.x < 32) {
        #pragma unroll
        for (int k = 0; k < 5; k++) {
            float vv = (lane < TPB / 32) ? sm[lane][k] : 0.0f;
            #pragma unroll
            for (int off = 4; off; off >>= 1)
                vv += __shfl_xor_sync(0xffffffffu, vv, off);
            if (lane == 0) g_partials[blockIdx.x * 5 + k] = vv;
        }
    }

    // ── last-block final reduction ──
    __shared__ bool isLast;
    if (threadIdx.x == 0) {
        __threadfence();
        unsigned old = atomicAdd(&g_count, 1u);
        isLast = (old == gridDim.x - 1u);
    }
    __syncthreads();
    if (isLast) {
        const volatile float* gp = g_partials;
        float loc[5] = {0.f, 0.f, 0.f, 0.f, 0.f};
        for (int j = threadIdx.x; j < (int)gridDim.x; j += TPB) {
            #pragma unroll
            for (int k = 0; k < 5; k++) loc[k] += gp[j * 5 + k];
        }
        __shared__ float red[TPB];
        float tot[5];
        #pragma unroll
        for (int k = 0; k < 5; k++) {
            red[threadIdx.x] = loc[k];
            __syncthreads();
            for (int st = TPB / 2; st; st >>= 1) {
                if (threadIdx.x < st) red[threadIdx.x] += red[threadIdx.x + st];
                __syncthreads();
            }
            tot[k] = red[0];
            __syncthreads();
        }
        if (threadIdx.x == 0) {
            constexpr float LN2 = 0.69314718055994530942f;
            float cnt   = fmaxf(tot[4], 1.0f);
            float inv_c = 1.0f / cnt;
            out[0] = -LN2 * (tot[0] * inv_obj_div
                             + (tot[1] + tot[2]) * 0.5f * inv_c
                             + tot[3] * inv_c);
            g_count = 0;
        }
    }
}

extern "C" void kernel_launch(void* const* d_in, const int* in_sizes, int n_in,
                              void* d_out, int out_size) {
    const float* x  = (const float*)d_in[0];
    const float* tg = (const float*)d_in[1];
    const int rows  = in_sizes[0] / C;     // B * S
    const int Bn    = rows / S_TOT;        // batch
    const float inv_obj_div = 1.0f / ((float)Bn * (float)S1 * (float)C);

    int dev = 0, smCount = 148, bpm = 4;
    cudaGetDevice(&dev);
    cudaDeviceGetAttribute(&smCount, cudaDevAttrMultiProcessorCount, dev);
    cudaOccupancyMaxActiveBlocksPerMultiprocessor(&bpm, yolo_fused, TPB, 0);
    int nb = smCount * (bpm > 0 ? bpm : 1);
    if (nb > MAXNB) nb = MAXNB;

    yolo_fused<<<nb, TPB>>>(x, tg, Bn, inv_obj_div, (float*)d_out);
}